// round 13
// baseline (speedup 1.0000x reference)
#include <cuda_runtime.h>

// ---------------------------------------------------------------------------
// ResidualBlock: x + BN2(capsconv2(BN1(capsconv1(x))))
// B=2, C=64, H=W=96, capsules 8x8, kernel 3x3 pad 1, routing iters = 3
// ---------------------------------------------------------------------------

static constexpr int Bv = 2;
static constexpr int Hv = 96;
static constexpr int Wv = 96;
static constexpr int Nv = Hv * Wv;  // 9216

typedef unsigned long long ull;

__device__ __forceinline__ ull pack2(float lo, float hi) {
    ull r; asm("mov.b64 %0,{%1,%2};" : "=l"(r) : "f"(lo), "f"(hi)); return r;
}
__device__ __forceinline__ void unpack2(ull v, float& lo, float& hi) {
    asm("mov.b64 {%0,%1},%2;" : "=f"(lo), "=f"(hi) : "l"(v));
}
__device__ __forceinline__ ull fma2(ull a, ull b, ull c) {
    ull d; asm("fma.rn.f32x2 %0,%1,%2,%3;" : "=l"(d) : "l"(a), "l"(b), "l"(c)); return d;
}
__device__ __forceinline__ ull mul2(ull a, ull b) {
    ull d; asm("mul.rn.f32x2 %0,%1,%2;" : "=l"(d) : "l"(a), "l"(b)); return d;
}
__device__ __forceinline__ ull add2(ull a, ull b) {
    ull d; asm("add.rn.f32x2 %0,%1,%2;" : "=l"(d) : "l"(a), "l"(b)); return d;
}
__device__ __forceinline__ ull shfl_xor2(ull v, int m) {
    float lo, hi; unpack2(v, lo, hi);
    lo = __shfl_xor_sync(0xffffffffu, lo, m);
    hi = __shfl_xor_sync(0xffffffffu, hi, m);
    return pack2(lo, hi);
}

// scratch (device globals; no allocation allowed)
__device__ float g_xT[Bv * Nv * 64];     // x in NHWC
__device__ float g_buf1[Bv * Nv * 64];   // conv1 output, NHWC (pre-BN)
__device__ float g_buf2[Bv * Nv * 64];   // conv2 output, NHWC (pre-BN)
__device__ float g_part[64 * 64 * 2];    // per-block partial (sum, sumsq)
__device__ float g_w2p[8 * 4608];        // w2 with BN1 scale folded
__device__ float g_bias2[8 * 576];       // per (o,j,m) bias from BN1 shift

// ---------------------------------------------------------------------------
// NCHW -> NHWC transpose of x. grid 288, block 256
// ---------------------------------------------------------------------------
__global__ __launch_bounds__(256) void nchw_to_nhwc_kernel(const float* __restrict__ x) {
    __shared__ float tile[64][65];
    const int bb   = blockIdx.x / 144;
    const int t    = blockIdx.x % 144;
    const int base = t * 64;
    const int tid  = threadIdx.x;
#pragma unroll
    for (int it = 0; it < 16; ++it) {
        int idx = it * 256 + tid;
        int c = idx >> 6, s = idx & 63;
        tile[s][c] = x[(bb * 64 + c) * Nv + base + s];
    }
    __syncthreads();
#pragma unroll
    for (int it = 0; it < 16; ++it) {
        int idx = it * 256 + tid;
        int s = idx >> 6, c = idx & 63;
        g_xT[(bb * Nv + base + s) * 64 + c] = tile[s][c];
    }
}

// ---------------------------------------------------------------------------
// Fused capsule conv + dynamic routing.
// grid (192, 8): x -> (b, row h); y -> output capsule o. block = 128 (4 warps).
// 6 chunks of 16 pixel columns; warp handles 4 pixels; lane = q*8+g where
// q = pixel quarter, g = input capsule i. Lane owns j = g*9 + k (k=0..8), all m.
// Weights in smem with XOR-4 m-half swizzle for j>=36 (stride 576, no pad).
// Layer-2 bias read via __ldg (L1-resident). n1 recomputed per iteration.
// __launch_bounds__(128,5): 5 blocks/SM (20 warps) — regs capped at 102.
// ---------------------------------------------------------------------------
static constexpr int WSTR = 576;          // per-l weight stride (words, no pad)
static constexpr int WINW = 3 * 18 * 64;  // window floats = 3456

template <bool FIRST>
__global__ __launch_bounds__(128, 5) void conv_route_kernel(const float* __restrict__ wt) {
    __shared__ __align__(16) float sW[8 * WSTR];     // 18432 B
    __shared__ __align__(16) float sWin[2][WINW];    // 27648 B -> total 46080 B

    const int o   = blockIdx.y;
    const int b   = blockIdx.x / 96;
    const int h   = blockIdx.x % 96;
    const int tid = threadIdx.x;

    const float* __restrict__ in   = FIRST ? g_xT : g_buf1;
    const float* __restrict__ wsrc = FIRST ? wt : (const float*)g_w2p;
    float* __restrict__ outbuf     = FIRST ? g_buf1 : g_buf2;

    // ---- cp.async window loader (zero-fill OOB) ----
    auto issue_chunk = [&](int cw, int buf) {
        const int w0 = cw * 16;
        float* dst = sWin[buf];
#pragma unroll
        for (int it = 0; it < 7; ++it) {
            int f4 = it * 128 + tid;
            if (f4 < 864) {
                int cg = (f4 & 15) * 4;            // channel group start
                int t  = f4 >> 4;                  // dh*18+dw, 0..53
                int dh = t / 18, dw = t % 18;
                int hh = h + dh - 1;
                int ww = w0 + dw - 1;
                bool ok = (hh >= 0) && (hh < Hv) && (ww >= 0) && (ww < Wv);
                const float* src = ok ? &in[((size_t)(b * Nv + hh * Wv + ww)) * 64 + cg] : in;
                int csw = cg ^ ((cg & 32) >> 3);   // XOR-4 swizzle on upper half
                unsigned sa = (unsigned)__cvta_generic_to_shared(&dst[t * 64 + csw]);
                int sz = ok ? 16 : 0;
                asm volatile("cp.async.cg.shared.global [%0], [%1], 16, %2;\n"
                             :: "r"(sa), "l"(src), "r"(sz) : "memory");
            }
        }
        asm volatile("cp.async.commit_group;\n" ::: "memory");
    };

    issue_chunk(0, 0);

    // ---- weights: wsrc[o*4608 + j*64 + l*8 + m] -> sW[l*576 + j*8 + (m ^ xr)]
    //      where xr = 4 for j >= 36 (bank de-conflict swizzle, no padding)
    for (int s = tid; s < 4608; s += 128) {
        int j = s >> 6;
        int l = (s >> 3) & 7;
        int m = s & 7;
        int xr = (j >= 36) ? 4 : 0;
        sW[l * WSTR + j * 8 + (m ^ xr)] = wsrc[o * 4608 + s];
    }

    asm volatile("cp.async.wait_group 0;\n" ::: "memory");
    __syncthreads();

    const int wid  = tid >> 5;
    const int lane = tid & 31;
    const int q    = lane >> 3;   // pixel quarter
    const int g    = lane & 7;    // input capsule i
    const int p    = wid * 4 + q; // pixel col within chunk (0..15)

    // lane-constant swizzled channel offsets for a-loads
    const int cz0 = (g * 8)     ^ (((g * 8)     & 32) >> 3);
    const int cz1 = (g * 8 + 4) ^ (((g * 8 + 4) & 32) >> 3);
    const int xr  = (g >= 4) ? 4 : 0;   // j = 9g+k >= 36  <=>  g >= 4
    const int jo  = 72 * g;             // weight base word (k=0)

    for (int cw = 0; cw < 6; ++cw) {
        const int cur = cw & 1;
        if (cw < 5) issue_chunk(cw + 1, cur ^ 1);

        const float* win = sWin[cur];
        const int ww0 = cw * 16 + p - 1;  // leftmost patch column for this pixel

        // ---- priors pr[k][mpair], init = masked __ldg bias (layer2) or 0
        ull pr[9][4];
        if (FIRST) {
#pragma unroll
            for (int k = 0; k < 9; ++k)
#pragma unroll
                for (int mq = 0; mq < 4; ++mq) pr[k][mq] = 0ull;
        } else {
#pragma unroll
            for (int k = 0; k < 9; ++k) {
                int dh = k / 3, dw = k % 3;
                int hh = h + dh - 1;
                bool v = (hh >= 0) && (hh < Hv) && ((unsigned)(ww0 + dw) < (unsigned)Wv);
                if (v) {
                    const ulonglong2* bj = reinterpret_cast<const ulonglong2*>(
                        &g_bias2[o * 576 + (g * 9 + k) * 8]);
                    ulonglong2 b0 = __ldg(bj);
                    ulonglong2 b1 = __ldg(bj + 1);
                    pr[k][0] = b0.x; pr[k][1] = b0.y;
                    pr[k][2] = b1.x; pr[k][3] = b1.y;
                } else {
#pragma unroll
                    for (int mq = 0; mq < 4; ++mq) pr[k][mq] = 0ull;
                }
            }
        }

#pragma unroll
        for (int k = 0; k < 9; ++k) {
            const int dh = k / 3, dw = k % 3;
            const float* arow = &win[(dh * 18 + p + dw) * 64];
            float4 aA = *reinterpret_cast<const float4*>(&arow[cz0]);
            float4 aB = *reinterpret_cast<const float4*>(&arow[cz1]);
            float av[8] = {aA.x, aA.y, aA.z, aA.w, aB.x, aB.y, aB.z, aB.w};
#pragma unroll
            for (int l = 0; l < 8; ++l) {
                const float* wb = &sW[l * WSTR + jo + 8 * k];
                ulonglong2 w01 = *reinterpret_cast<const ulonglong2*>(&wb[xr]);
                ulonglong2 w23 = *reinterpret_cast<const ulonglong2*>(&wb[xr ^ 4]);
                ull ap = pack2(av[l], av[l]);
                pr[k][0] = fma2(ap, w01.x, pr[k][0]);
                pr[k][1] = fma2(ap, w01.y, pr[k][1]);
                pr[k][2] = fma2(ap, w23.x, pr[k][2]);
                pr[k][3] = fma2(ap, w23.y, pr[k][3]);
            }
        }

        // ---- init: u = sum over 72 j of priors (unnormalized), S = 72
        ull u[4];
#pragma unroll
        for (int mq = 0; mq < 4; ++mq) {
            ull s = pr[0][mq];
#pragma unroll
            for (int k = 1; k < 9; ++k) s = add2(pr[k][mq], s);
#pragma unroll
            for (int off = 1; off < 8; off <<= 1) s = add2(s, shfl_xor2(s, off));
            u[mq] = s;
        }
        float S = 72.0f;

        // ---- 3 routing iterations with deferred normalization; n1 recomputed
        //      in-loop (saves 9 live registers; bit-identical value)
#pragma unroll
        for (int it = 0; it < 3; ++it) {
            float S2 = S * S;
            ull t2 = mul2(u[0], u[0]);
            t2 = fma2(u[1], u[1], t2);
            t2 = fma2(u[2], u[2], t2);
            t2 = fma2(u[3], u[3], t2);
            float n2lo, n2hi; unpack2(t2, n2lo, n2hi);
            float n2u = n2lo + n2hi;           // |u|^2
            float epsS2 = 1e-8f * S2;

            float esum = 0.f;
            ull acc[4] = {0ull, 0ull, 0ull, 0ull};
#pragma unroll
            for (int k = 0; k < 9; ++k) {
                // n1_k = |pr_k|^2 (recomputed)
                ull tn = mul2(pr[k][0], pr[k][0]);
                tn = fma2(pr[k][1], pr[k][1], tn);
                tn = fma2(pr[k][2], pr[k][2], tn);
                tn = fma2(pr[k][3], pr[k][3], tn);
                float nlo, nhi; unpack2(tn, nlo, nhi);
                float n1k = nlo + nhi;

                ull td = mul2(pr[k][0], u[0]);
                td = fma2(pr[k][1], u[1], td);
                td = fma2(pr[k][2], u[2], td);
                td = fma2(pr[k][3], u[3], td);
                float dlo, dhi; unpack2(td, dlo, dhi);
                float du  = dlo + dhi;
                float num = du * S;
                float den = fmaxf(fmaf(n1k, S2, n2u) - num, epsS2);
                float e   = __expf(__fdividef(num, den));
                esum += e;
                ull pjp = pack2(e, e);
                acc[0] = fma2(pjp, pr[k][0], acc[0]);
                acc[1] = fma2(pjp, pr[k][1], acc[1]);
                acc[2] = fma2(pjp, pr[k][2], acc[2]);
                acc[3] = fma2(pjp, pr[k][3], acc[3]);
            }

            // concurrent butterflies (esum + acc) — independent chains
#pragma unroll
            for (int off = 1; off < 8; off <<= 1) {
                esum += __shfl_xor_sync(0xffffffffu, esum, off);
                acc[0] = add2(acc[0], shfl_xor2(acc[0], off));
                acc[1] = add2(acc[1], shfl_xor2(acc[1], off));
                acc[2] = add2(acc[2], shfl_xor2(acc[2], off));
                acc[3] = add2(acc[3], shfl_xor2(acc[3], off));
            }
            u[0] = acc[0]; u[1] = acc[1]; u[2] = acc[2]; u[3] = acc[3];
            S = esum;
        }

        if (g == 0) {
            float inv = __fdividef(1.0f, S);
            float o0, o1, o2, o3, o4, o5, o6, o7;
            unpack2(u[0], o0, o1);
            unpack2(u[1], o2, o3);
            unpack2(u[2], o4, o5);
            unpack2(u[3], o6, o7);
            int ww = cw * 16 + p;
            float* dst = &outbuf[((size_t)(b * Nv + h * Wv + ww)) * 64 + o * 8];
            reinterpret_cast<float4*>(dst)[0] =
                make_float4(o0 * inv, o1 * inv, o2 * inv, o3 * inv);
            reinterpret_cast<float4*>(dst)[1] =
                make_float4(o4 * inv, o5 * inv, o6 * inv, o7 * inv);
        }

        if (cw < 5) {
            asm volatile("cp.async.wait_group 0;\n" ::: "memory");
            __syncthreads();
        }
    }
}

// ---------------------------------------------------------------------------
// BN stats stage 1: per-block partial sum / sumsq per channel. grid 64, block 512.
// ---------------------------------------------------------------------------
template <int WHICH>
__global__ __launch_bounds__(512) void bn_stats_kernel() {
    __shared__ float s1[512];
    __shared__ float s2[512];
    const float* __restrict__ buf = (WHICH == 1) ? g_buf1 : g_buf2;
    const int tid = threadIdx.x;
    const int base = blockIdx.x * 18432;
    float a = 0.f, q = 0.f;
#pragma unroll
    for (int it = 0; it < 36; ++it) {
        float v = buf[base + it * 512 + tid];
        a += v;
        q = fmaf(v, v, q);
    }
    s1[tid] = a;
    s2[tid] = q;
    __syncthreads();
    if (tid < 64) {
        float sa = 0.f, sq = 0.f;
#pragma unroll
        for (int r = 0; r < 8; ++r) {
            sa += s1[tid + r * 64];
            sq += s2[tid + r * 64];
        }
        g_part[(blockIdx.x * 64 + tid) * 2 + 0] = sa;
        g_part[(blockIdx.x * 64 + tid) * 2 + 1] = sq;
    }
}

// ---------------------------------------------------------------------------
// wprep: BN1 affine from g_part, fold into conv2 weights + bias. grid 144, blk 256.
// ---------------------------------------------------------------------------
__global__ __launch_bounds__(256) void wprep_kernel(const float* __restrict__ w2,
                                                    const float* __restrict__ gamma,
                                                    const float* __restrict__ beta) {
    __shared__ float red[4][128];
    __shared__ float sSc[64];
    __shared__ float sBi[64];
    const int tid = threadIdx.x;
    const int c   = tid & 63;
    const int grp = tid >> 6;
    float s = 0.f, qv = 0.f;
#pragma unroll
    for (int u = 0; u < 16; ++u) {
        int kb = grp * 16 + u;
        s  += g_part[(kb * 64 + c) * 2 + 0];
        qv += g_part[(kb * 64 + c) * 2 + 1];
    }
    red[grp][c]      = s;
    red[grp][64 + c] = qv;
    __syncthreads();
    if (tid < 64) {
        float sa = 0.f, sq = 0.f;
#pragma unroll
        for (int r = 0; r < 4; ++r) { sa += red[r][tid]; sq += red[r][64 + tid]; }
        const float invM = 1.0f / (float)(Bv * Nv);
        float mean = sa * invM;
        float var  = fmaf(-mean, mean, sq * invM);
        float inv  = rsqrtf(var + 1e-5f);
        float scv  = gamma[tid] * inv;
        sSc[tid] = scv;
        sBi[tid] = beta[tid] - mean * scv;
    }
    __syncthreads();

    int idx = blockIdx.x * 256 + tid;  // 0..36863
    {
        int i = (idx / 576) & 7;
        int l = (idx >> 3) & 7;
        g_w2p[idx] = w2[idx] * sSc[i * 8 + l];
    }
    if (idx < 4608) {
        int o2 = idx / 576;
        int jm = idx % 576;
        int j  = jm >> 3;
        int m2 = jm & 7;
        int i2 = j / 9;
        float sb = 0.f;
#pragma unroll
        for (int l = 0; l < 8; ++l)
            sb = fmaf(sBi[i2 * 8 + l], w2[o2 * 4608 + j * 64 + l * 8 + m2], sb);
        g_bias2[idx] = sb;
    }
}

// ---------------------------------------------------------------------------
// Final: out(NCHW) = x + BN2(g_buf2), NHWC->NCHW transpose. BN2 finalize is
// fused: each block recomputes the small stat reduction from g_part. grid 288.
// ---------------------------------------------------------------------------
__global__ __launch_bounds__(256) void final_kernel(const float* __restrict__ x,
                                                    const float* __restrict__ gamma,
                                                    const float* __restrict__ beta,
                                                    float* __restrict__ out) {
    __shared__ float tile[64][65];
    __shared__ float red[4][128];
    __shared__ float sSB[128];
    const int bb   = blockIdx.x / 144;
    const int t    = blockIdx.x % 144;
    const int base = t * 64;
    const int tid  = threadIdx.x;

    // fused BN2 finalize (identical deterministic reduction in every block)
    {
        const int c   = tid & 63;
        const int grp = tid >> 6;
        float s = 0.f, qv = 0.f;
#pragma unroll
        for (int u = 0; u < 16; ++u) {
            int kb = grp * 16 + u;
            s  += g_part[(kb * 64 + c) * 2 + 0];
            qv += g_part[(kb * 64 + c) * 2 + 1];
        }
        red[grp][c]      = s;
        red[grp][64 + c] = qv;
        __syncthreads();
        if (tid < 64) {
            float sa = 0.f, sq = 0.f;
#pragma unroll
            for (int r = 0; r < 4; ++r) { sa += red[r][tid]; sq += red[r][64 + tid]; }
            const float invM = 1.0f / (float)(Bv * Nv);
            float mean = sa * invM;
            float var  = fmaf(-mean, mean, sq * invM);
            float inv  = rsqrtf(var + 1e-5f);
            float scv  = gamma[tid] * inv;
            sSB[tid]      = scv;
            sSB[64 + tid] = beta[tid] - mean * scv;
        }
        __syncthreads();
    }

#pragma unroll
    for (int it = 0; it < 16; ++it) {
        int idx = it * 256 + tid;
        int s = idx >> 6, c = idx & 63;
        tile[s][c] = fmaf(g_buf2[(bb * Nv + base + s) * 64 + c], sSB[c], sSB[64 + c]);
    }
    __syncthreads();
#pragma unroll
    for (int it = 0; it < 16; ++it) {
        int idx = it * 256 + tid;
        int c = idx >> 6, s = idx & 63;
        int off = (bb * 64 + c) * Nv + base + s;
        out[off] = x[off] + tile[s][c];
    }
}

// ---------------------------------------------------------------------------
extern "C" void kernel_launch(void* const* d_in, const int* in_sizes, int n_in,
                              void* d_out, int out_size) {
    const float* x  = (const float*)d_in[0];
    const float* w1 = (const float*)d_in[1];
    const float* g1 = (const float*)d_in[2];
    const float* b1 = (const float*)d_in[3];
    const float* w2 = (const float*)d_in[4];
    const float* g2 = (const float*)d_in[5];
    const float* b2 = (const float*)d_in[6];
    float* out = (float*)d_out;

    nchw_to_nhwc_kernel<<<288, 256>>>(x);
    conv_route_kernel<true><<<dim3(192, 8), 128>>>(w1);
    bn_stats_kernel<1><<<64, 512>>>();
    wprep_kernel<<<144, 256>>>(w2, g1, b1);
    conv_route_kernel<false><<<dim3(192, 8), 128>>>(w2);  // uses g_w2p internally
    bn_stats_kernel<2><<<64, 512>>>();
    final_kernel<<<288, 256>>>(x, g2, b2, out);
}

// round 14
// speedup vs baseline: 1.2105x; 1.2105x over previous
#include <cuda_runtime.h>

// ---------------------------------------------------------------------------
// ResidualBlock: x + BN2(capsconv2(BN1(capsconv1(x))))
// B=2, C=64, H=W=96, capsules 8x8, kernel 3x3 pad 1, routing iters = 3
// Final configuration (empirical optimum over 13 measured rounds):
//  - NHWC layout; fused conv+routing kernel; 8 lanes per pixel, in-lane
//    j-reductions; f32x2 packed math; cp.async double-buffered windows;
//    BN1 folded into conv2 weights/bias; deferred softmax normalization;
//    fused exp/accumulate loop; BN2 finalize fused into the epilogue.
// ---------------------------------------------------------------------------

static constexpr int Bv = 2;
static constexpr int Hv = 96;
static constexpr int Wv = 96;
static constexpr int Nv = Hv * Wv;  // 9216

typedef unsigned long long ull;

__device__ __forceinline__ ull pack2(float lo, float hi) {
    ull r; asm("mov.b64 %0,{%1,%2};" : "=l"(r) : "f"(lo), "f"(hi)); return r;
}
__device__ __forceinline__ void unpack2(ull v, float& lo, float& hi) {
    asm("mov.b64 {%0,%1},%2;" : "=f"(lo), "=f"(hi) : "l"(v));
}
__device__ __forceinline__ ull fma2(ull a, ull b, ull c) {
    ull d; asm("fma.rn.f32x2 %0,%1,%2,%3;" : "=l"(d) : "l"(a), "l"(b), "l"(c)); return d;
}
__device__ __forceinline__ ull mul2(ull a, ull b) {
    ull d; asm("mul.rn.f32x2 %0,%1,%2;" : "=l"(d) : "l"(a), "l"(b)); return d;
}
__device__ __forceinline__ ull add2(ull a, ull b) {
    ull d; asm("add.rn.f32x2 %0,%1,%2;" : "=l"(d) : "l"(a), "l"(b)); return d;
}
__device__ __forceinline__ ull shfl_xor2(ull v, int m) {
    float lo, hi; unpack2(v, lo, hi);
    lo = __shfl_xor_sync(0xffffffffu, lo, m);
    hi = __shfl_xor_sync(0xffffffffu, hi, m);
    return pack2(lo, hi);
}

// scratch (device globals; no allocation allowed)
__device__ float g_xT[Bv * Nv * 64];     // x in NHWC
__device__ float g_buf1[Bv * Nv * 64];   // conv1 output, NHWC (pre-BN)
__device__ float g_buf2[Bv * Nv * 64];   // conv2 output, NHWC (pre-BN)
__device__ float g_part[64 * 64 * 2];    // per-block partial (sum, sumsq)
__device__ float g_w2p[8 * 4608];        // w2 with BN1 scale folded
__device__ float g_bias2[8 * 576];       // per (o,j,m) bias from BN1 shift

// ---------------------------------------------------------------------------
// NCHW -> NHWC transpose of x. grid 288, block 256
// ---------------------------------------------------------------------------
__global__ __launch_bounds__(256) void nchw_to_nhwc_kernel(const float* __restrict__ x) {
    __shared__ float tile[64][65];
    const int bb   = blockIdx.x / 144;
    const int t    = blockIdx.x % 144;
    const int base = t * 64;
    const int tid  = threadIdx.x;
#pragma unroll
    for (int it = 0; it < 16; ++it) {
        int idx = it * 256 + tid;
        int c = idx >> 6, s = idx & 63;
        tile[s][c] = x[(bb * 64 + c) * Nv + base + s];
    }
    __syncthreads();
#pragma unroll
    for (int it = 0; it < 16; ++it) {
        int idx = it * 256 + tid;
        int s = idx >> 6, c = idx & 63;
        g_xT[(bb * Nv + base + s) * 64 + c] = tile[s][c];
    }
}

// ---------------------------------------------------------------------------
// Fused capsule conv + dynamic routing.
// grid (192, 8): x -> (b, row h); y -> output capsule o. block = 128 (4 warps).
// 6 chunks of 16 pixel columns; warp handles 4 pixels; lane = q*8+g where
// q = pixel quarter, g = input capsule i. Lane owns j = g*9 + k (k=0..8), all m.
// cp.async double-buffered input window. BN1 folded into conv2 weights/bias
// (bias masked by patch validity). Deferred softmax normalization; the
// exp-weight accumulation is fused into the same k-loop (no ev[] array).
// ---------------------------------------------------------------------------
static constexpr int WSTR = 580;          // per-l weight stride (words)
static constexpr int WINW = 3 * 18 * 64;  // window floats = 3456

template <bool FIRST>
__global__ __launch_bounds__(128, 4) void conv_route_kernel(const float* __restrict__ wt) {
    __shared__ __align__(16) float sW[8 * WSTR];     // 18560 B
    __shared__ __align__(16) float sWin[2][WINW];    // 27648 B
    __shared__ __align__(16) float sB[576];          //  2304 B

    const int o   = blockIdx.y;
    const int b   = blockIdx.x / 96;
    const int h   = blockIdx.x % 96;
    const int tid = threadIdx.x;

    const float* __restrict__ in   = FIRST ? g_xT : g_buf1;
    const float* __restrict__ wsrc = FIRST ? wt : (const float*)g_w2p;
    float* __restrict__ outbuf     = FIRST ? g_buf1 : g_buf2;

    // ---- cp.async window loader (zero-fill OOB) ----
    auto issue_chunk = [&](int cw, int buf) {
        const int w0 = cw * 16;
        float* dst = sWin[buf];
#pragma unroll
        for (int it = 0; it < 7; ++it) {
            int f4 = it * 128 + tid;
            if (f4 < 864) {
                int cg = (f4 & 15) * 4;            // channel group start
                int t  = f4 >> 4;                  // dh*18+dw, 0..53
                int dh = t / 18, dw = t % 18;
                int hh = h + dh - 1;
                int ww = w0 + dw - 1;
                bool ok = (hh >= 0) && (hh < Hv) && (ww >= 0) && (ww < Wv);
                const float* src = ok ? &in[((size_t)(b * Nv + hh * Wv + ww)) * 64 + cg] : in;
                int csw = cg ^ ((cg & 32) >> 3);   // XOR-4 swizzle on upper half
                unsigned sa = (unsigned)__cvta_generic_to_shared(&dst[t * 64 + csw]);
                int sz = ok ? 16 : 0;
                asm volatile("cp.async.cg.shared.global [%0], [%1], 16, %2;\n"
                             :: "r"(sa), "l"(src), "r"(sz) : "memory");
            }
        }
        asm volatile("cp.async.commit_group;\n" ::: "memory");
    };

    issue_chunk(0, 0);

    // ---- weights: wsrc[o*4608 + j*64 + l*8 + m] -> sW[l*WSTR + j*8 + 4*(j/36) + m]
    for (int s = tid; s < 4608; s += 128) {
        int j = s >> 6;
        int l = (s >> 3) & 7;
        int m = s & 7;
        sW[l * WSTR + j * 8 + 4 * (j / 36) + m] = wsrc[o * 4608 + s];
    }
    // ---- bias (layer 2 only)
    if (!FIRST) {
        for (int s = tid; s < 576; s += 128) sB[s] = g_bias2[o * 576 + s];
    }

    asm volatile("cp.async.wait_group 0;\n" ::: "memory");
    __syncthreads();

    const int wid  = tid >> 5;
    const int lane = tid & 31;
    const int q    = lane >> 3;   // pixel quarter
    const int g    = lane & 7;    // input capsule i
    const int p    = wid * 4 + q; // pixel col within chunk (0..15)

    // lane-constant swizzled channel offsets for a-loads
    const int cz0 = (g * 8)     ^ (((g * 8)     & 32) >> 3);
    const int cz1 = (g * 8 + 4) ^ (((g * 8 + 4) & 32) >> 3);
    const int jo  = 72 * g + 4 * (g >> 2);  // swizzled weight base (k=0)

    // per-k row validity (h direction)
    bool hvalid[3];
#pragma unroll
    for (int dh = 0; dh < 3; ++dh) {
        int hh = h + dh - 1;
        hvalid[dh] = (hh >= 0) && (hh < Hv);
    }

    for (int cw = 0; cw < 6; ++cw) {
        const int cur = cw & 1;
        if (cw < 5) issue_chunk(cw + 1, cur ^ 1);

        const float* win = sWin[cur];
        const int ww0 = cw * 16 + p - 1;  // leftmost patch column for this pixel

        // ---- priors pr[k][mpair], init = bias (masked by patch validity) or 0
        ull pr[9][4];
        if (FIRST) {
#pragma unroll
            for (int k = 0; k < 9; ++k)
#pragma unroll
                for (int mq = 0; mq < 4; ++mq) pr[k][mq] = 0ull;
        } else {
#pragma unroll
            for (int k = 0; k < 9; ++k) {
                int dh = k / 3, dw = k % 3;
                bool v = hvalid[dh] && ((unsigned)(ww0 + dw) < (unsigned)Wv);
                if (v) {
                    const ulonglong2* bj =
                        reinterpret_cast<const ulonglong2*>(&sB[(g * 9 + k) * 8]);
                    ulonglong2 b0 = bj[0];
                    ulonglong2 b1 = bj[1];
                    pr[k][0] = b0.x; pr[k][1] = b0.y;
                    pr[k][2] = b1.x; pr[k][3] = b1.y;
                } else {
#pragma unroll
                    for (int mq = 0; mq < 4; ++mq) pr[k][mq] = 0ull;
                }
            }
        }

#pragma unroll
        for (int k = 0; k < 9; ++k) {
            const int dh = k / 3, dw = k % 3;
            const float* arow = &win[(dh * 18 + p + dw) * 64];
            float4 aA = *reinterpret_cast<const float4*>(&arow[cz0]);
            float4 aB = *reinterpret_cast<const float4*>(&arow[cz1]);
            float av[8] = {aA.x, aA.y, aA.z, aA.w, aB.x, aB.y, aB.z, aB.w};
#pragma unroll
            for (int l = 0; l < 8; ++l) {
                const ulonglong2* wp =
                    reinterpret_cast<const ulonglong2*>(&sW[l * WSTR + jo + 8 * k]);
                ulonglong2 w01 = wp[0];
                ulonglong2 w23 = wp[1];
                ull ap = pack2(av[l], av[l]);
                pr[k][0] = fma2(ap, w01.x, pr[k][0]);
                pr[k][1] = fma2(ap, w01.y, pr[k][1]);
                pr[k][2] = fma2(ap, w23.x, pr[k][2]);
                pr[k][3] = fma2(ap, w23.y, pr[k][3]);
            }
        }

        // ---- n1[k] = |pr_k|^2 (in-lane)
        float n1[9];
#pragma unroll
        for (int k = 0; k < 9; ++k) {
            ull t = mul2(pr[k][0], pr[k][0]);
            t = fma2(pr[k][1], pr[k][1], t);
            t = fma2(pr[k][2], pr[k][2], t);
            t = fma2(pr[k][3], pr[k][3], t);
            float lo, hi; unpack2(t, lo, hi);
            n1[k] = lo + hi;
        }

        // ---- init: u = sum over 72 j of priors (unnormalized), S = 72
        ull u[4];
#pragma unroll
        for (int mq = 0; mq < 4; ++mq) {
            ull s = pr[0][mq];
#pragma unroll
            for (int k = 1; k < 9; ++k) s = add2(pr[k][mq], s);
#pragma unroll
            for (int off = 1; off < 8; off <<= 1) s = add2(s, shfl_xor2(s, off));
            u[mq] = s;
        }
        float S = 72.0f;

        // ---- 3 routing iterations with deferred normalization; exp-weight
        //      accumulation fused into the same k-loop
#pragma unroll
        for (int it = 0; it < 3; ++it) {
            float S2 = S * S;
            ull t2 = mul2(u[0], u[0]);
            t2 = fma2(u[1], u[1], t2);
            t2 = fma2(u[2], u[2], t2);
            t2 = fma2(u[3], u[3], t2);
            float n2lo, n2hi; unpack2(t2, n2lo, n2hi);
            float n2u = n2lo + n2hi;           // |u|^2
            float epsS2 = 1e-8f * S2;

            float esum = 0.f;
            ull acc[4] = {0ull, 0ull, 0ull, 0ull};
#pragma unroll
            for (int k = 0; k < 9; ++k) {
                ull td = mul2(pr[k][0], u[0]);
                td = fma2(pr[k][1], u[1], td);
                td = fma2(pr[k][2], u[2], td);
                td = fma2(pr[k][3], u[3], td);
                float dlo, dhi; unpack2(td, dlo, dhi);
                float du  = dlo + dhi;
                float num = du * S;
                float den = fmaxf(fmaf(n1[k], S2, n2u) - num, epsS2);
                float e   = __expf(__fdividef(num, den));
                esum += e;
                ull pjp = pack2(e, e);
                acc[0] = fma2(pjp, pr[k][0], acc[0]);
                acc[1] = fma2(pjp, pr[k][1], acc[1]);
                acc[2] = fma2(pjp, pr[k][2], acc[2]);
                acc[3] = fma2(pjp, pr[k][3], acc[3]);
            }

            // concurrent butterflies (esum + acc) — independent chains
#pragma unroll
            for (int off = 1; off < 8; off <<= 1) {
                esum += __shfl_xor_sync(0xffffffffu, esum, off);
                acc[0] = add2(acc[0], shfl_xor2(acc[0], off));
                acc[1] = add2(acc[1], shfl_xor2(acc[1], off));
                acc[2] = add2(acc[2], shfl_xor2(acc[2], off));
                acc[3] = add2(acc[3], shfl_xor2(acc[3], off));
            }
            u[0] = acc[0]; u[1] = acc[1]; u[2] = acc[2]; u[3] = acc[3];
            S = esum;
        }

        if (g == 0) {
            float inv = __fdividef(1.0f, S);
            float o0, o1, o2, o3, o4, o5, o6, o7;
            unpack2(u[0], o0, o1);
            unpack2(u[1], o2, o3);
            unpack2(u[2], o4, o5);
            unpack2(u[3], o6, o7);
            int ww = cw * 16 + p;
            float* dst = &outbuf[((size_t)(b * Nv + h * Wv + ww)) * 64 + o * 8];
            reinterpret_cast<float4*>(dst)[0] =
                make_float4(o0 * inv, o1 * inv, o2 * inv, o3 * inv);
            reinterpret_cast<float4*>(dst)[1] =
                make_float4(o4 * inv, o5 * inv, o6 * inv, o7 * inv);
        }

        if (cw < 5) {
            asm volatile("cp.async.wait_group 0;\n" ::: "memory");
            __syncthreads();
        }
    }
}

// ---------------------------------------------------------------------------
// BN stats stage 1: per-block partial sum / sumsq per channel. grid 64, block 512.
// ---------------------------------------------------------------------------
template <int WHICH>
__global__ __launch_bounds__(512) void bn_stats_kernel() {
    __shared__ float s1[512];
    __shared__ float s2[512];
    const float* __restrict__ buf = (WHICH == 1) ? g_buf1 : g_buf2;
    const int tid = threadIdx.x;
    const int base = blockIdx.x * 18432;
    float a = 0.f, q = 0.f;
#pragma unroll
    for (int it = 0; it < 36; ++it) {
        float v = buf[base + it * 512 + tid];
        a += v;
        q = fmaf(v, v, q);
    }
    s1[tid] = a;
    s2[tid] = q;
    __syncthreads();
    if (tid < 64) {
        float sa = 0.f, sq = 0.f;
#pragma unroll
        for (int r = 0; r < 8; ++r) {
            sa += s1[tid + r * 64];
            sq += s2[tid + r * 64];
        }
        g_part[(blockIdx.x * 64 + tid) * 2 + 0] = sa;
        g_part[(blockIdx.x * 64 + tid) * 2 + 1] = sq;
    }
}

// ---------------------------------------------------------------------------
// wprep: BN1 affine from g_part, fold into conv2 weights + bias. grid 144, blk 256.
// ---------------------------------------------------------------------------
__global__ __launch_bounds__(256) void wprep_kernel(const float* __restrict__ w2,
                                                    const float* __restrict__ gamma,
                                                    const float* __restrict__ beta) {
    __shared__ float red[4][128];
    __shared__ float sSc[64];
    __shared__ float sBi[64];
    const int tid = threadIdx.x;
    const int c   = tid & 63;
    const int grp = tid >> 6;
    float s = 0.f, qv = 0.f;
#pragma unroll
    for (int u = 0; u < 16; ++u) {
        int kb = grp * 16 + u;
        s  += g_part[(kb * 64 + c) * 2 + 0];
        qv += g_part[(kb * 64 + c) * 2 + 1];
    }
    red[grp][c]      = s;
    red[grp][64 + c] = qv;
    __syncthreads();
    if (tid < 64) {
        float sa = 0.f, sq = 0.f;
#pragma unroll
        for (int r = 0; r < 4; ++r) { sa += red[r][tid]; sq += red[r][64 + tid]; }
        const float invM = 1.0f / (float)(Bv * Nv);
        float mean = sa * invM;
        float var  = fmaf(-mean, mean, sq * invM);
        float inv  = rsqrtf(var + 1e-5f);
        float scv  = gamma[tid] * inv;
        sSc[tid] = scv;
        sBi[tid] = beta[tid] - mean * scv;
    }
    __syncthreads();

    int idx = blockIdx.x * 256 + tid;  // 0..36863
    {
        int i = (idx / 576) & 7;
        int l = (idx >> 3) & 7;
        g_w2p[idx] = w2[idx] * sSc[i * 8 + l];
    }
    if (idx < 4608) {
        int o2 = idx / 576;
        int jm = idx % 576;
        int j  = jm >> 3;
        int m2 = jm & 7;
        int i2 = j / 9;
        float sb = 0.f;
#pragma unroll
        for (int l = 0; l < 8; ++l)
            sb = fmaf(sBi[i2 * 8 + l], w2[o2 * 4608 + j * 64 + l * 8 + m2], sb);
        g_bias2[idx] = sb;
    }
}

// ---------------------------------------------------------------------------
// Final: out(NCHW) = x + BN2(g_buf2), NHWC->NCHW transpose. BN2 finalize is
// fused: each block recomputes the small stat reduction from g_part. grid 288.
// ---------------------------------------------------------------------------
__global__ __launch_bounds__(256) void final_kernel(const float* __restrict__ x,
                                                    const float* __restrict__ gamma,
                                                    const float* __restrict__ beta,
                                                    float* __restrict__ out) {
    __shared__ float tile[64][65];
    __shared__ float red[4][128];
    __shared__ float sSB[128];
    const int bb   = blockIdx.x / 144;
    const int t    = blockIdx.x % 144;
    const int base = t * 64;
    const int tid  = threadIdx.x;

    // fused BN2 finalize (identical deterministic reduction in every block)
    {
        const int c   = tid & 63;
        const int grp = tid >> 6;
        float s = 0.f, qv = 0.f;
#pragma unroll
        for (int u = 0; u < 16; ++u) {
            int kb = grp * 16 + u;
            s  += g_part[(kb * 64 + c) * 2 + 0];
            qv += g_part[(kb * 64 + c) * 2 + 1];
        }
        red[grp][c]      = s;
        red[grp][64 + c] = qv;
        __syncthreads();
        if (tid < 64) {
            float sa = 0.f, sq = 0.f;
#pragma unroll
            for (int r = 0; r < 4; ++r) { sa += red[r][tid]; sq += red[r][64 + tid]; }
            const float invM = 1.0f / (float)(Bv * Nv);
            float mean = sa * invM;
            float var  = fmaf(-mean, mean, sq * invM);
            float inv  = rsqrtf(var + 1e-5f);
            float scv  = gamma[tid] * inv;
            sSB[tid]      = scv;
            sSB[64 + tid] = beta[tid] - mean * scv;
        }
        __syncthreads();
    }

#pragma unroll
    for (int it = 0; it < 16; ++it) {
        int idx = it * 256 + tid;
        int s = idx >> 6, c = idx & 63;
        tile[s][c] = fmaf(g_buf2[(bb * Nv + base + s) * 64 + c], sSB[c], sSB[64 + c]);
    }
    __syncthreads();
#pragma unroll
    for (int it = 0; it < 16; ++it) {
        int idx = it * 256 + tid;
        int c = idx >> 6, s = idx & 63;
        int off = (bb * 64 + c) * Nv + base + s;
        out[off] = x[off] + tile[s][c];
    }
}

// ---------------------------------------------------------------------------
extern "C" void kernel_launch(void* const* d_in, const int* in_sizes, int n_in,
                              void* d_out, int out_size) {
    const float* x  = (const float*)d_in[0];
    const float* w1 = (const float*)d_in[1];
    const float* g1 = (const float*)d_in[2];
    const float* b1 = (const float*)d_in[3];
    const float* w2 = (const float*)d_in[4];
    const float* g2 = (const float*)d_in[5];
    const float* b2 = (const float*)d_in[6];
    float* out = (float*)d_out;

    nchw_to_nhwc_kernel<<<288, 256>>>(x);
    conv_route_kernel<true><<<dim3(192, 8), 128>>>(w1);
    bn_stats_kernel<1><<<64, 512>>>();
    wprep_kernel<<<144, 256>>>(w2, g1, b1);
    conv_route_kernel<false><<<dim3(192, 8), 128>>>(w2);  // uses g_w2p internally
    bn_stats_kernel<2><<<64, 512>>>();
    final_kernel<<<288, 256>>>(x, g2, b2, out);
}

// round 15
// speedup vs baseline: 1.2191x; 1.0071x over previous
#include <cuda_runtime.h>

// ---------------------------------------------------------------------------
// ResidualBlock: x + BN2(capsconv2(BN1(capsconv1(x))))
// B=2, C=64, H=W=96, capsules 8x8, kernel 3x3 pad 1, routing iters = 3
// Final configuration (empirical optimum over 14 measured rounds):
//  - NHWC layout; fused conv+routing kernel; 8 lanes per pixel, in-lane
//    j-reductions; f32x2 packed math; cp.async double-buffered windows;
//    BN1 folded into conv2 weights/bias (bias via __ldg, L1-resident);
//    deferred softmax normalization; fused exp/accumulate loop;
//    BN2 finalize fused into the residual epilogue.
// ---------------------------------------------------------------------------

static constexpr int Bv = 2;
static constexpr int Hv = 96;
static constexpr int Wv = 96;
static constexpr int Nv = Hv * Wv;  // 9216

typedef unsigned long long ull;

__device__ __forceinline__ ull pack2(float lo, float hi) {
    ull r; asm("mov.b64 %0,{%1,%2};" : "=l"(r) : "f"(lo), "f"(hi)); return r;
}
__device__ __forceinline__ void unpack2(ull v, float& lo, float& hi) {
    asm("mov.b64 {%0,%1},%2;" : "=f"(lo), "=f"(hi) : "l"(v));
}
__device__ __forceinline__ ull fma2(ull a, ull b, ull c) {
    ull d; asm("fma.rn.f32x2 %0,%1,%2,%3;" : "=l"(d) : "l"(a), "l"(b), "l"(c)); return d;
}
__device__ __forceinline__ ull mul2(ull a, ull b) {
    ull d; asm("mul.rn.f32x2 %0,%1,%2;" : "=l"(d) : "l"(a), "l"(b)); return d;
}
__device__ __forceinline__ ull add2(ull a, ull b) {
    ull d; asm("add.rn.f32x2 %0,%1,%2;" : "=l"(d) : "l"(a), "l"(b)); return d;
}
__device__ __forceinline__ ull shfl_xor2(ull v, int m) {
    float lo, hi; unpack2(v, lo, hi);
    lo = __shfl_xor_sync(0xffffffffu, lo, m);
    hi = __shfl_xor_sync(0xffffffffu, hi, m);
    return pack2(lo, hi);
}

// scratch (device globals; no allocation allowed)
__device__ float g_xT[Bv * Nv * 64];     // x in NHWC
__device__ float g_buf1[Bv * Nv * 64];   // conv1 output, NHWC (pre-BN)
__device__ float g_buf2[Bv * Nv * 64];   // conv2 output, NHWC (pre-BN)
__device__ float g_part[64 * 64 * 2];    // per-block partial (sum, sumsq)
__device__ float g_w2p[8 * 4608];        // w2 with BN1 scale folded
__device__ float g_bias2[8 * 576];       // per (o,j,m) bias from BN1 shift

// ---------------------------------------------------------------------------
// NCHW -> NHWC transpose of x. grid 288, block 256
// ---------------------------------------------------------------------------
__global__ __launch_bounds__(256) void nchw_to_nhwc_kernel(const float* __restrict__ x) {
    __shared__ float tile[64][65];
    const int bb   = blockIdx.x / 144;
    const int t    = blockIdx.x % 144;
    const int base = t * 64;
    const int tid  = threadIdx.x;
#pragma unroll
    for (int it = 0; it < 16; ++it) {
        int idx = it * 256 + tid;
        int c = idx >> 6, s = idx & 63;
        tile[s][c] = x[(bb * 64 + c) * Nv + base + s];
    }
    __syncthreads();
#pragma unroll
    for (int it = 0; it < 16; ++it) {
        int idx = it * 256 + tid;
        int s = idx >> 6, c = idx & 63;
        g_xT[(bb * Nv + base + s) * 64 + c] = tile[s][c];
    }
}

// ---------------------------------------------------------------------------
// Fused capsule conv + dynamic routing.
// grid (192, 8): x -> (b, row h); y -> output capsule o. block = 128 (4 warps).
// 6 chunks of 16 pixel columns; warp handles 4 pixels; lane = q*8+g where
// q = pixel quarter, g = input capsule i. Lane owns j = g*9 + k (k=0..8), all m.
// cp.async double-buffered input window. BN1 folded into conv2 weights/bias
// (bias masked by patch validity, read via __ldg). Deferred softmax
// normalization; exp-weight accumulation fused into the k-loop.
// ---------------------------------------------------------------------------
static constexpr int WSTR = 580;          // per-l weight stride (words)
static constexpr int WINW = 3 * 18 * 64;  // window floats = 3456

template <bool FIRST>
__global__ __launch_bounds__(128, 4) void conv_route_kernel(const float* __restrict__ wt) {
    __shared__ __align__(16) float sW[8 * WSTR];     // 18560 B
    __shared__ __align__(16) float sWin[2][WINW];    // 27648 B

    const int o   = blockIdx.y;
    const int b   = blockIdx.x / 96;
    const int h   = blockIdx.x % 96;
    const int tid = threadIdx.x;

    const float* __restrict__ in   = FIRST ? g_xT : g_buf1;
    const float* __restrict__ wsrc = FIRST ? wt : (const float*)g_w2p;
    float* __restrict__ outbuf     = FIRST ? g_buf1 : g_buf2;

    // ---- cp.async window loader (zero-fill OOB) ----
    auto issue_chunk = [&](int cw, int buf) {
        const int w0 = cw * 16;
        float* dst = sWin[buf];
#pragma unroll
        for (int it = 0; it < 7; ++it) {
            int f4 = it * 128 + tid;
            if (f4 < 864) {
                int cg = (f4 & 15) * 4;            // channel group start
                int t  = f4 >> 4;                  // dh*18+dw, 0..53
                int dh = t / 18, dw = t % 18;
                int hh = h + dh - 1;
                int ww = w0 + dw - 1;
                bool ok = (hh >= 0) && (hh < Hv) && (ww >= 0) && (ww < Wv);
                const float* src = ok ? &in[((size_t)(b * Nv + hh * Wv + ww)) * 64 + cg] : in;
                int csw = cg ^ ((cg & 32) >> 3);   // XOR-4 swizzle on upper half
                unsigned sa = (unsigned)__cvta_generic_to_shared(&dst[t * 64 + csw]);
                int sz = ok ? 16 : 0;
                asm volatile("cp.async.cg.shared.global [%0], [%1], 16, %2;\n"
                             :: "r"(sa), "l"(src), "r"(sz) : "memory");
            }
        }
        asm volatile("cp.async.commit_group;\n" ::: "memory");
    };

    issue_chunk(0, 0);

    // ---- weights: wsrc[o*4608 + j*64 + l*8 + m] -> sW[l*WSTR + j*8 + 4*(j/36) + m]
    for (int s = tid; s < 4608; s += 128) {
        int j = s >> 6;
        int l = (s >> 3) & 7;
        int m = s & 7;
        sW[l * WSTR + j * 8 + 4 * (j / 36) + m] = wsrc[o * 4608 + s];
    }

    asm volatile("cp.async.wait_group 0;\n" ::: "memory");
    __syncthreads();

    const int wid  = tid >> 5;
    const int lane = tid & 31;
    const int q    = lane >> 3;   // pixel quarter
    const int g    = lane & 7;    // input capsule i
    const int p    = wid * 4 + q; // pixel col within chunk (0..15)

    // lane-constant swizzled channel offsets for a-loads
    const int cz0 = (g * 8)     ^ (((g * 8)     & 32) >> 3);
    const int cz1 = (g * 8 + 4) ^ (((g * 8 + 4) & 32) >> 3);
    const int jo  = 72 * g + 4 * (g >> 2);  // swizzled weight base (k=0)

    // per-k row validity (h direction)
    bool hvalid[3];
#pragma unroll
    for (int dh = 0; dh < 3; ++dh) {
        int hh = h + dh - 1;
        hvalid[dh] = (hh >= 0) && (hh < Hv);
    }

    for (int cw = 0; cw < 6; ++cw) {
        const int cur = cw & 1;
        if (cw < 5) issue_chunk(cw + 1, cur ^ 1);

        const float* win = sWin[cur];
        const int ww0 = cw * 16 + p - 1;  // leftmost patch column for this pixel

        // ---- priors pr[k][mpair], init = bias (masked by patch validity) or 0
        ull pr[9][4];
        if (FIRST) {
#pragma unroll
            for (int k = 0; k < 9; ++k)
#pragma unroll
                for (int mq = 0; mq < 4; ++mq) pr[k][mq] = 0ull;
        } else {
#pragma unroll
            for (int k = 0; k < 9; ++k) {
                int dh = k / 3, dw = k % 3;
                bool v = hvalid[dh] && ((unsigned)(ww0 + dw) < (unsigned)Wv);
                if (v) {
                    const ulonglong2* bj = reinterpret_cast<const ulonglong2*>(
                        &g_bias2[o * 576 + (g * 9 + k) * 8]);
                    ulonglong2 b0 = __ldg(bj);
                    ulonglong2 b1 = __ldg(bj + 1);
                    pr[k][0] = b0.x; pr[k][1] = b0.y;
                    pr[k][2] = b1.x; pr[k][3] = b1.y;
                } else {
#pragma unroll
                    for (int mq = 0; mq < 4; ++mq) pr[k][mq] = 0ull;
                }
            }
        }

#pragma unroll
        for (int k = 0; k < 9; ++k) {
            const int dh = k / 3, dw = k % 3;
            const float* arow = &win[(dh * 18 + p + dw) * 64];
            float4 aA = *reinterpret_cast<const float4*>(&arow[cz0]);
            float4 aB = *reinterpret_cast<const float4*>(&arow[cz1]);
            float av[8] = {aA.x, aA.y, aA.z, aA.w, aB.x, aB.y, aB.z, aB.w};
#pragma unroll
            for (int l = 0; l < 8; ++l) {
                const ulonglong2* wp =
                    reinterpret_cast<const ulonglong2*>(&sW[l * WSTR + jo + 8 * k]);
                ulonglong2 w01 = wp[0];
                ulonglong2 w23 = wp[1];
                ull ap = pack2(av[l], av[l]);
                pr[k][0] = fma2(ap, w01.x, pr[k][0]);
                pr[k][1] = fma2(ap, w01.y, pr[k][1]);
                pr[k][2] = fma2(ap, w23.x, pr[k][2]);
                pr[k][3] = fma2(ap, w23.y, pr[k][3]);
            }
        }

        // ---- n1[k] = |pr_k|^2 (in-lane)
        float n1[9];
#pragma unroll
        for (int k = 0; k < 9; ++k) {
            ull t = mul2(pr[k][0], pr[k][0]);
            t = fma2(pr[k][1], pr[k][1], t);
            t = fma2(pr[k][2], pr[k][2], t);
            t = fma2(pr[k][3], pr[k][3], t);
            float lo, hi; unpack2(t, lo, hi);
            n1[k] = lo + hi;
        }

        // ---- init: u = sum over 72 j of priors (unnormalized), S = 72
        ull u[4];
#pragma unroll
        for (int mq = 0; mq < 4; ++mq) {
            ull s = pr[0][mq];
#pragma unroll
            for (int k = 1; k < 9; ++k) s = add2(pr[k][mq], s);
#pragma unroll
            for (int off = 1; off < 8; off <<= 1) s = add2(s, shfl_xor2(s, off));
            u[mq] = s;
        }
        float S = 72.0f;

        // ---- 3 routing iterations with deferred normalization; exp-weight
        //      accumulation fused into the same k-loop
#pragma unroll
        for (int it = 0; it < 3; ++it) {
            float S2 = S * S;
            ull t2 = mul2(u[0], u[0]);
            t2 = fma2(u[1], u[1], t2);
            t2 = fma2(u[2], u[2], t2);
            t2 = fma2(u[3], u[3], t2);
            float n2lo, n2hi; unpack2(t2, n2lo, n2hi);
            float n2u = n2lo + n2hi;           // |u|^2
            float epsS2 = 1e-8f * S2;

            float esum = 0.f;
            ull acc[4] = {0ull, 0ull, 0ull, 0ull};
#pragma unroll
            for (int k = 0; k < 9; ++k) {
                ull td = mul2(pr[k][0], u[0]);
                td = fma2(pr[k][1], u[1], td);
                td = fma2(pr[k][2], u[2], td);
                td = fma2(pr[k][3], u[3], td);
                float dlo, dhi; unpack2(td, dlo, dhi);
                float du  = dlo + dhi;
                float num = du * S;
                float den = fmaxf(fmaf(n1[k], S2, n2u) - num, epsS2);
                float e   = __expf(__fdividef(num, den));
                esum += e;
                ull pjp = pack2(e, e);
                acc[0] = fma2(pjp, pr[k][0], acc[0]);
                acc[1] = fma2(pjp, pr[k][1], acc[1]);
                acc[2] = fma2(pjp, pr[k][2], acc[2]);
                acc[3] = fma2(pjp, pr[k][3], acc[3]);
            }

            // concurrent butterflies (esum + acc) — independent chains
#pragma unroll
            for (int off = 1; off < 8; off <<= 1) {
                esum += __shfl_xor_sync(0xffffffffu, esum, off);
                acc[0] = add2(acc[0], shfl_xor2(acc[0], off));
                acc[1] = add2(acc[1], shfl_xor2(acc[1], off));
                acc[2] = add2(acc[2], shfl_xor2(acc[2], off));
                acc[3] = add2(acc[3], shfl_xor2(acc[3], off));
            }
            u[0] = acc[0]; u[1] = acc[1]; u[2] = acc[2]; u[3] = acc[3];
            S = esum;
        }

        if (g == 0) {
            float inv = __fdividef(1.0f, S);
            float o0, o1, o2, o3, o4, o5, o6, o7;
            unpack2(u[0], o0, o1);
            unpack2(u[1], o2, o3);
            unpack2(u[2], o4, o5);
            unpack2(u[3], o6, o7);
            int ww = cw * 16 + p;
            float* dst = &outbuf[((size_t)(b * Nv + h * Wv + ww)) * 64 + o * 8];
            reinterpret_cast<float4*>(dst)[0] =
                make_float4(o0 * inv, o1 * inv, o2 * inv, o3 * inv);
            reinterpret_cast<float4*>(dst)[1] =
                make_float4(o4 * inv, o5 * inv, o6 * inv, o7 * inv);
        }

        if (cw < 5) {
            asm volatile("cp.async.wait_group 0;\n" ::: "memory");
            __syncthreads();
        }
    }
}

// ---------------------------------------------------------------------------
// BN stats stage 1: per-block partial sum / sumsq per channel. grid 64, block 512.
// ---------------------------------------------------------------------------
template <int WHICH>
__global__ __launch_bounds__(512) void bn_stats_kernel() {
    __shared__ float s1[512];
    __shared__ float s2[512];
    const float* __restrict__ buf = (WHICH == 1) ? g_buf1 : g_buf2;
    const int tid = threadIdx.x;
    const int base = blockIdx.x * 18432;
    float a = 0.f, q = 0.f;
#pragma unroll
    for (int it = 0; it < 36; ++it) {
        float v = buf[base + it * 512 + tid];
        a += v;
        q = fmaf(v, v, q);
    }
    s1[tid] = a;
    s2[tid] = q;
    __syncthreads();
    if (tid < 64) {
        float sa = 0.f, sq = 0.f;
#pragma unroll
        for (int r = 0; r < 8; ++r) {
            sa += s1[tid + r * 64];
            sq += s2[tid + r * 64];
        }
        g_part[(blockIdx.x * 64 + tid) * 2 + 0] = sa;
        g_part[(blockIdx.x * 64 + tid) * 2 + 1] = sq;
    }
}

// ---------------------------------------------------------------------------
// wprep: BN1 affine from g_part, fold into conv2 weights + bias. grid 144, blk 256.
// ---------------------------------------------------------------------------
__global__ __launch_bounds__(256) void wprep_kernel(const float* __restrict__ w2,
                                                    const float* __restrict__ gamma,
                                                    const float* __restrict__ beta) {
    __shared__ float red[4][128];
    __shared__ float sSc[64];
    __shared__ float sBi[64];
    const int tid = threadIdx.x;
    const int c   = tid & 63;
    const int grp = tid >> 6;
    float s = 0.f, qv = 0.f;
#pragma unroll
    for (int u = 0; u < 16; ++u) {
        int kb = grp * 16 + u;
        s  += g_part[(kb * 64 + c) * 2 + 0];
        qv += g_part[(kb * 64 + c) * 2 + 1];
    }
    red[grp][c]      = s;
    red[grp][64 + c] = qv;
    __syncthreads();
    if (tid < 64) {
        float sa = 0.f, sq = 0.f;
#pragma unroll
        for (int r = 0; r < 4; ++r) { sa += red[r][tid]; sq += red[r][64 + tid]; }
        const float invM = 1.0f / (float)(Bv * Nv);
        float mean = sa * invM;
        float var  = fmaf(-mean, mean, sq * invM);
        float inv  = rsqrtf(var + 1e-5f);
        float scv  = gamma[tid] * inv;
        sSc[tid] = scv;
        sBi[tid] = beta[tid] - mean * scv;
    }
    __syncthreads();

    int idx = blockIdx.x * 256 + tid;  // 0..36863
    {
        int i = (idx / 576) & 7;
        int l = (idx >> 3) & 7;
        g_w2p[idx] = w2[idx] * sSc[i * 8 + l];
    }
    if (idx < 4608) {
        int o2 = idx / 576;
        int jm = idx % 576;
        int j  = jm >> 3;
        int m2 = jm & 7;
        int i2 = j / 9;
        float sb = 0.f;
#pragma unroll
        for (int l = 0; l < 8; ++l)
            sb = fmaf(sBi[i2 * 8 + l], w2[o2 * 4608 + j * 64 + l * 8 + m2], sb);
        g_bias2[idx] = sb;
    }
}

// ---------------------------------------------------------------------------
// Final: out(NCHW) = x + BN2(g_buf2), NHWC->NCHW transpose. BN2 finalize is
// fused: each block recomputes the small stat reduction from g_part. grid 288.
// ---------------------------------------------------------------------------
__global__ __launch_bounds__(256) void final_kernel(const float* __restrict__ x,
                                                    const float* __restrict__ gamma,
                                                    const float* __restrict__ beta,
                                                    float* __restrict__ out) {
    __shared__ float tile[64][65];
    __shared__ float red[4][128];
    __shared__ float sSB[128];
    const int bb   = blockIdx.x / 144;
    const int t    = blockIdx.x % 144;
    const int base = t * 64;
    const int tid  = threadIdx.x;

    // fused BN2 finalize (identical deterministic reduction in every block)
    {
        const int c   = tid & 63;
        const int grp = tid >> 6;
        float s = 0.f, qv = 0.f;
#pragma unroll
        for (int u = 0; u < 16; ++u) {
            int kb = grp * 16 + u;
            s  += g_part[(kb * 64 + c) * 2 + 0];
            qv += g_part[(kb * 64 + c) * 2 + 1];
        }
        red[grp][c]      = s;
        red[grp][64 + c] = qv;
        __syncthreads();
        if (tid < 64) {
            float sa = 0.f, sq = 0.f;
#pragma unroll
            for (int r = 0; r < 4; ++r) { sa += red[r][tid]; sq += red[r][64 + tid]; }
            const float invM = 1.0f / (float)(Bv * Nv);
            float mean = sa * invM;
            float var  = fmaf(-mean, mean, sq * invM);
            float inv  = rsqrtf(var + 1e-5f);
            float scv  = gamma[tid] * inv;
            sSB[tid]      = scv;
            sSB[64 + tid] = beta[tid] - mean * scv;
        }
        __syncthreads();
    }

#pragma unroll
    for (int it = 0; it < 16; ++it) {
        int idx = it * 256 + tid;
        int s = idx >> 6, c = idx & 63;
        tile[s][c] = fmaf(g_buf2[(bb * Nv + base + s) * 64 + c], sSB[c], sSB[64 + c]);
    }
    __syncthreads();
#pragma unroll
    for (int it = 0; it < 16; ++it) {
        int idx = it * 256 + tid;
        int c = idx >> 6, s = idx & 63;
        int off = (bb * 64 + c) * Nv + base + s;
        out[off] = x[off] + tile[s][c];
    }
}

// ---------------------------------------------------------------------------
extern "C" void kernel_launch(void* const* d_in, const int* in_sizes, int n_in,
                              void* d_out, int out_size) {
    const float* x  = (const float*)d_in[0];
    const float* w1 = (const float*)d_in[1];
    const float* g1 = (const float*)d_in[2];
    const float* b1 = (const float*)d_in[3];
    const float* w2 = (const float*)d_in[4];
    const float* g2 = (const float*)d_in[5];
    const float* b2 = (const float*)d_in[6];
    float* out = (float*)d_out;

    nchw_to_nhwc_kernel<<<288, 256>>>(x);
    conv_route_kernel<true><<<dim3(192, 8), 128>>>(w1);
    bn_stats_kernel<1><<<64, 512>>>();
    wprep_kernel<<<144, 256>>>(w2, g1, b1);
    conv_route_kernel<false><<<dim3(192, 8), 128>>>(w2);  // uses g_w2p internally
    bn_stats_kernel<2><<<64, 512>>>();
    final_kernel<<<288, 256>>>(x, g2, b2, out);
}

// round 16
// speedup vs baseline: 1.2299x; 1.0089x over previous
#include <cuda_runtime.h>

// ---------------------------------------------------------------------------
// ResidualBlock: x + BN2(capsconv2(BN1(capsconv1(x))))
// B=2, C=64, H=W=96, capsules 8x8, kernel 3x3 pad 1, routing iters = 3
// Final configuration (empirical optimum over 15 measured rounds):
//  - NHWC layout; fused conv+routing kernel; 8 lanes per pixel, in-lane
//    j-reductions; f32x2 packed math; cp.async double-buffered windows;
//    BN1 folded into conv2 weights/bias (bias via __ldg, L1-resident);
//    deferred softmax normalization; fused exp/accumulate loop;
//    vectorized (128-bit) weight staging; BN2 finalize fused into epilogue.
// ---------------------------------------------------------------------------

static constexpr int Bv = 2;
static constexpr int Hv = 96;
static constexpr int Wv = 96;
static constexpr int Nv = Hv * Wv;  // 9216

typedef unsigned long long ull;

__device__ __forceinline__ ull pack2(float lo, float hi) {
    ull r; asm("mov.b64 %0,{%1,%2};" : "=l"(r) : "f"(lo), "f"(hi)); return r;
}
__device__ __forceinline__ void unpack2(ull v, float& lo, float& hi) {
    asm("mov.b64 {%0,%1},%2;" : "=f"(lo), "=f"(hi) : "l"(v));
}
__device__ __forceinline__ ull fma2(ull a, ull b, ull c) {
    ull d; asm("fma.rn.f32x2 %0,%1,%2,%3;" : "=l"(d) : "l"(a), "l"(b), "l"(c)); return d;
}
__device__ __forceinline__ ull mul2(ull a, ull b) {
    ull d; asm("mul.rn.f32x2 %0,%1,%2;" : "=l"(d) : "l"(a), "l"(b)); return d;
}
__device__ __forceinline__ ull add2(ull a, ull b) {
    ull d; asm("add.rn.f32x2 %0,%1,%2;" : "=l"(d) : "l"(a), "l"(b)); return d;
}
__device__ __forceinline__ ull shfl_xor2(ull v, int m) {
    float lo, hi; unpack2(v, lo, hi);
    lo = __shfl_xor_sync(0xffffffffu, lo, m);
    hi = __shfl_xor_sync(0xffffffffu, hi, m);
    return pack2(lo, hi);
}

// scratch (device globals; no allocation allowed)
__device__ float g_xT[Bv * Nv * 64];     // x in NHWC
__device__ float g_buf1[Bv * Nv * 64];   // conv1 output, NHWC (pre-BN)
__device__ float g_buf2[Bv * Nv * 64];   // conv2 output, NHWC (pre-BN)
__device__ float g_part[64 * 64 * 2];    // per-block partial (sum, sumsq)
__device__ float g_w2p[8 * 4608];        // w2 with BN1 scale folded
__device__ float g_bias2[8 * 576];       // per (o,j,m) bias from BN1 shift

// ---------------------------------------------------------------------------
// NCHW -> NHWC transpose of x. grid 288, block 256
// ---------------------------------------------------------------------------
__global__ __launch_bounds__(256) void nchw_to_nhwc_kernel(const float* __restrict__ x) {
    __shared__ float tile[64][65];
    const int bb   = blockIdx.x / 144;
    const int t    = blockIdx.x % 144;
    const int base = t * 64;
    const int tid  = threadIdx.x;
#pragma unroll
    for (int it = 0; it < 16; ++it) {
        int idx = it * 256 + tid;
        int c = idx >> 6, s = idx & 63;
        tile[s][c] = x[(bb * 64 + c) * Nv + base + s];
    }
    __syncthreads();
#pragma unroll
    for (int it = 0; it < 16; ++it) {
        int idx = it * 256 + tid;
        int s = idx >> 6, c = idx & 63;
        g_xT[(bb * Nv + base + s) * 64 + c] = tile[s][c];
    }
}

// ---------------------------------------------------------------------------
// Fused capsule conv + dynamic routing.
// grid (192, 8): x -> (b, row h); y -> output capsule o. block = 128 (4 warps).
// 6 chunks of 16 pixel columns; warp handles 4 pixels; lane = q*8+g where
// q = pixel quarter, g = input capsule i. Lane owns j = g*9 + k (k=0..8), all m.
// cp.async double-buffered input window. BN1 folded into conv2 weights/bias
// (bias masked by patch validity, read via __ldg). Deferred softmax
// normalization; exp-weight accumulation fused into the k-loop.
// ---------------------------------------------------------------------------
static constexpr int WSTR = 580;          // per-l weight stride (words)
static constexpr int WINW = 3 * 18 * 64;  // window floats = 3456

template <bool FIRST>
__global__ __launch_bounds__(128, 4) void conv_route_kernel(const float* __restrict__ wt) {
    __shared__ __align__(16) float sW[8 * WSTR];     // 18560 B
    __shared__ __align__(16) float sWin[2][WINW];    // 27648 B

    const int o   = blockIdx.y;
    const int b   = blockIdx.x / 96;
    const int h   = blockIdx.x % 96;
    const int tid = threadIdx.x;

    const float* __restrict__ in   = FIRST ? g_xT : g_buf1;
    const float* __restrict__ wsrc = FIRST ? wt : (const float*)g_w2p;
    float* __restrict__ outbuf     = FIRST ? g_buf1 : g_buf2;

    // ---- cp.async window loader (zero-fill OOB) ----
    auto issue_chunk = [&](int cw, int buf) {
        const int w0 = cw * 16;
        float* dst = sWin[buf];
#pragma unroll
        for (int it = 0; it < 7; ++it) {
            int f4 = it * 128 + tid;
            if (f4 < 864) {
                int cg = (f4 & 15) * 4;            // channel group start
                int t  = f4 >> 4;                  // dh*18+dw, 0..53
                int dh = t / 18, dw = t % 18;
                int hh = h + dh - 1;
                int ww = w0 + dw - 1;
                bool ok = (hh >= 0) && (hh < Hv) && (ww >= 0) && (ww < Wv);
                const float* src = ok ? &in[((size_t)(b * Nv + hh * Wv + ww)) * 64 + cg] : in;
                int csw = cg ^ ((cg & 32) >> 3);   // XOR-4 swizzle on upper half
                unsigned sa = (unsigned)__cvta_generic_to_shared(&dst[t * 64 + csw]);
                int sz = ok ? 16 : 0;
                asm volatile("cp.async.cg.shared.global [%0], [%1], 16, %2;\n"
                             :: "r"(sa), "l"(src), "r"(sz) : "memory");
            }
        }
        asm volatile("cp.async.commit_group;\n" ::: "memory");
    };

    issue_chunk(0, 0);

    // ---- weights, vectorized: 4 consecutive floats share (j,l) and start at
    //      m in {0,4}; smem target 16B-aligned -> LDG.128 + STS.128
    {
        const float4* wsrc4 = reinterpret_cast<const float4*>(wsrc + o * 4608);
#pragma unroll
        for (int it = 0; it < 9; ++it) {
            int s4 = it * 128 + tid;       // 0..1151
            float4 v = __ldg(wsrc4 + s4);
            int s = s4 * 4;
            int j = s >> 6;
            int l = (s >> 3) & 7;
            int m = s & 7;                 // 0 or 4
            *reinterpret_cast<float4*>(&sW[l * WSTR + j * 8 + 4 * (j / 36) + m]) = v;
        }
    }

    asm volatile("cp.async.wait_group 0;\n" ::: "memory");
    __syncthreads();

    const int wid  = tid >> 5;
    const int lane = tid & 31;
    const int q    = lane >> 3;   // pixel quarter
    const int g    = lane & 7;    // input capsule i
    const int p    = wid * 4 + q; // pixel col within chunk (0..15)

    // lane-constant swizzled channel offsets for a-loads
    const int cz0 = (g * 8)     ^ (((g * 8)     & 32) >> 3);
    const int cz1 = (g * 8 + 4) ^ (((g * 8 + 4) & 32) >> 3);
    const int jo  = 72 * g + 4 * (g >> 2);  // swizzled weight base (k=0)

    // per-k row validity (h direction)
    bool hvalid[3];
#pragma unroll
    for (int dh = 0; dh < 3; ++dh) {
        int hh = h + dh - 1;
        hvalid[dh] = (hh >= 0) && (hh < Hv);
    }

    for (int cw = 0; cw < 6; ++cw) {
        const int cur = cw & 1;
        if (cw < 5) issue_chunk(cw + 1, cur ^ 1);

        const float* win = sWin[cur];
        const int ww0 = cw * 16 + p - 1;  // leftmost patch column for this pixel

        // ---- priors pr[k][mpair], init = bias (masked by patch validity) or 0
        ull pr[9][4];
        if (FIRST) {
#pragma unroll
            for (int k = 0; k < 9; ++k)
#pragma unroll
                for (int mq = 0; mq < 4; ++mq) pr[k][mq] = 0ull;
        } else {
#pragma unroll
            for (int k = 0; k < 9; ++k) {
                int dh = k / 3, dw = k % 3;
                bool v = hvalid[dh] && ((unsigned)(ww0 + dw) < (unsigned)Wv);
                if (v) {
                    const ulonglong2* bj = reinterpret_cast<const ulonglong2*>(
                        &g_bias2[o * 576 + (g * 9 + k) * 8]);
                    ulonglong2 b0 = __ldg(bj);
                    ulonglong2 b1 = __ldg(bj + 1);
                    pr[k][0] = b0.x; pr[k][1] = b0.y;
                    pr[k][2] = b1.x; pr[k][3] = b1.y;
                } else {
#pragma unroll
                    for (int mq = 0; mq < 4; ++mq) pr[k][mq] = 0ull;
                }
            }
        }

#pragma unroll
        for (int k = 0; k < 9; ++k) {
            const int dh = k / 3, dw = k % 3;
            const float* arow = &win[(dh * 18 + p + dw) * 64];
            float4 aA = *reinterpret_cast<const float4*>(&arow[cz0]);
            float4 aB = *reinterpret_cast<const float4*>(&arow[cz1]);
            float av[8] = {aA.x, aA.y, aA.z, aA.w, aB.x, aB.y, aB.z, aB.w};
#pragma unroll
            for (int l = 0; l < 8; ++l) {
                const ulonglong2* wp =
                    reinterpret_cast<const ulonglong2*>(&sW[l * WSTR + jo + 8 * k]);
                ulonglong2 w01 = wp[0];
                ulonglong2 w23 = wp[1];
                ull ap = pack2(av[l], av[l]);
                pr[k][0] = fma2(ap, w01.x, pr[k][0]);
                pr[k][1] = fma2(ap, w01.y, pr[k][1]);
                pr[k][2] = fma2(ap, w23.x, pr[k][2]);
                pr[k][3] = fma2(ap, w23.y, pr[k][3]);
            }
        }

        // ---- n1[k] = |pr_k|^2 (in-lane)
        float n1[9];
#pragma unroll
        for (int k = 0; k < 9; ++k) {
            ull t = mul2(pr[k][0], pr[k][0]);
            t = fma2(pr[k][1], pr[k][1], t);
            t = fma2(pr[k][2], pr[k][2], t);
            t = fma2(pr[k][3], pr[k][3], t);
            float lo, hi; unpack2(t, lo, hi);
            n1[k] = lo + hi;
        }

        // ---- init: u = sum over 72 j of priors (unnormalized), S = 72
        ull u[4];
#pragma unroll
        for (int mq = 0; mq < 4; ++mq) {
            ull s = pr[0][mq];
#pragma unroll
            for (int k = 1; k < 9; ++k) s = add2(pr[k][mq], s);
#pragma unroll
            for (int off = 1; off < 8; off <<= 1) s = add2(s, shfl_xor2(s, off));
            u[mq] = s;
        }
        float S = 72.0f;

        // ---- 3 routing iterations with deferred normalization; exp-weight
        //      accumulation fused into the same k-loop
#pragma unroll
        for (int it = 0; it < 3; ++it) {
            float S2 = S * S;
            ull t2 = mul2(u[0], u[0]);
            t2 = fma2(u[1], u[1], t2);
            t2 = fma2(u[2], u[2], t2);
            t2 = fma2(u[3], u[3], t2);
            float n2lo, n2hi; unpack2(t2, n2lo, n2hi);
            float n2u = n2lo + n2hi;           // |u|^2
            float epsS2 = 1e-8f * S2;

            float esum = 0.f;
            ull acc[4] = {0ull, 0ull, 0ull, 0ull};
#pragma unroll
            for (int k = 0; k < 9; ++k) {
                ull td = mul2(pr[k][0], u[0]);
                td = fma2(pr[k][1], u[1], td);
                td = fma2(pr[k][2], u[2], td);
                td = fma2(pr[k][3], u[3], td);
                float dlo, dhi; unpack2(td, dlo, dhi);
                float du  = dlo + dhi;
                float num = du * S;
                float den = fmaxf(fmaf(n1[k], S2, n2u) - num, epsS2);
                float e   = __expf(__fdividef(num, den));
                esum += e;
                ull pjp = pack2(e, e);
                acc[0] = fma2(pjp, pr[k][0], acc[0]);
                acc[1] = fma2(pjp, pr[k][1], acc[1]);
                acc[2] = fma2(pjp, pr[k][2], acc[2]);
                acc[3] = fma2(pjp, pr[k][3], acc[3]);
            }

            // concurrent butterflies (esum + acc) — independent chains
#pragma unroll
            for (int off = 1; off < 8; off <<= 1) {
                esum += __shfl_xor_sync(0xffffffffu, esum, off);
                acc[0] = add2(acc[0], shfl_xor2(acc[0], off));
                acc[1] = add2(acc[1], shfl_xor2(acc[1], off));
                acc[2] = add2(acc[2], shfl_xor2(acc[2], off));
                acc[3] = add2(acc[3], shfl_xor2(acc[3], off));
            }
            u[0] = acc[0]; u[1] = acc[1]; u[2] = acc[2]; u[3] = acc[3];
            S = esum;
        }

        if (g == 0) {
            float inv = __fdividef(1.0f, S);
            float o0, o1, o2, o3, o4, o5, o6, o7;
            unpack2(u[0], o0, o1);
            unpack2(u[1], o2, o3);
            unpack2(u[2], o4, o5);
            unpack2(u[3], o6, o7);
            int ww = cw * 16 + p;
            float* dst = &outbuf[((size_t)(b * Nv + h * Wv + ww)) * 64 + o * 8];
            reinterpret_cast<float4*>(dst)[0] =
                make_float4(o0 * inv, o1 * inv, o2 * inv, o3 * inv);
            reinterpret_cast<float4*>(dst)[1] =
                make_float4(o4 * inv, o5 * inv, o6 * inv, o7 * inv);
        }

        if (cw < 5) {
            asm volatile("cp.async.wait_group 0;\n" ::: "memory");
            __syncthreads();
        }
    }
}

// ---------------------------------------------------------------------------
// BN stats stage 1: per-block partial sum / sumsq per channel. grid 64, block 512.
// ---------------------------------------------------------------------------
template <int WHICH>
__global__ __launch_bounds__(512) void bn_stats_kernel() {
    __shared__ float s1[512];
    __shared__ float s2[512];
    const float* __restrict__ buf = (WHICH == 1) ? g_buf1 : g_buf2;
    const int tid = threadIdx.x;
    const int base = blockIdx.x * 18432;
    float a = 0.f, q = 0.f;
#pragma unroll
    for (int it = 0; it < 36; ++it) {
        float v = buf[base + it * 512 + tid];
        a += v;
        q = fmaf(v, v, q);
    }
    s1[tid] = a;
    s2[tid] = q;
    __syncthreads();
    if (tid < 64) {
        float sa = 0.f, sq = 0.f;
#pragma unroll
        for (int r = 0; r < 8; ++r) {
            sa += s1[tid + r * 64];
            sq += s2[tid + r * 64];
        }
        g_part[(blockIdx.x * 64 + tid) * 2 + 0] = sa;
        g_part[(blockIdx.x * 64 + tid) * 2 + 1] = sq;
    }
}

// ---------------------------------------------------------------------------
// wprep: BN1 affine from g_part, fold into conv2 weights + bias. grid 144, blk 256.
// ---------------------------------------------------------------------------
__global__ __launch_bounds__(256) void wprep_kernel(const float* __restrict__ w2,
                                                    const float* __restrict__ gamma,
                                                    const float* __restrict__ beta) {
    __shared__ float red[4][128];
    __shared__ float sSc[64];
    __shared__ float sBi[64];
    const int tid = threadIdx.x;
    const int c   = tid & 63;
    const int grp = tid >> 6;
    float s = 0.f, qv = 0.f;
#pragma unroll
    for (int u = 0; u < 16; ++u) {
        int kb = grp * 16 + u;
        s  += g_part[(kb * 64 + c) * 2 + 0];
        qv += g_part[(kb * 64 + c) * 2 + 1];
    }
    red[grp][c]      = s;
    red[grp][64 + c] = qv;
    __syncthreads();
    if (tid < 64) {
        float sa = 0.f, sq = 0.f;
#pragma unroll
        for (int r = 0; r < 4; ++r) { sa += red[r][tid]; sq += red[r][64 + tid]; }
        const float invM = 1.0f / (float)(Bv * Nv);
        float mean = sa * invM;
        float var  = fmaf(-mean, mean, sq * invM);
        float inv  = rsqrtf(var + 1e-5f);
        float scv  = gamma[tid] * inv;
        sSc[tid] = scv;
        sBi[tid] = beta[tid] - mean * scv;
    }
    __syncthreads();

    int idx = blockIdx.x * 256 + tid;  // 0..36863
    {
        int i = (idx / 576) & 7;
        int l = (idx >> 3) & 7;
        g_w2p[idx] = w2[idx] * sSc[i * 8 + l];
    }
    if (idx < 4608) {
        int o2 = idx / 576;
        int jm = idx % 576;
        int j  = jm >> 3;
        int m2 = jm & 7;
        int i2 = j / 9;
        float sb = 0.f;
#pragma unroll
        for (int l = 0; l < 8; ++l)
            sb = fmaf(sBi[i2 * 8 + l], w2[o2 * 4608 + j * 64 + l * 8 + m2], sb);
        g_bias2[idx] = sb;
    }
}

// ---------------------------------------------------------------------------
// Final: out(NCHW) = x + BN2(g_buf2), NHWC->NCHW transpose. BN2 finalize is
// fused: each block recomputes the small stat reduction from g_part. grid 288.
// ---------------------------------------------------------------------------
__global__ __launch_bounds__(256) void final_kernel(const float* __restrict__ x,
                                                    const float* __restrict__ gamma,
                                                    const float* __restrict__ beta,
                                                    float* __restrict__ out) {
    __shared__ float tile[64][65];
    __shared__ float red[4][128];
    __shared__ float sSB[128];
    const int bb   = blockIdx.x / 144;
    const int t    = blockIdx.x % 144;
    const int base = t * 64;
    const int tid  = threadIdx.x;

    // fused BN2 finalize (identical deterministic reduction in every block)
    {
        const int c   = tid & 63;
        const int grp = tid >> 6;
        float s = 0.f, qv = 0.f;
#pragma unroll
        for (int u = 0; u < 16; ++u) {
            int kb = grp * 16 + u;
            s  += g_part[(kb * 64 + c) * 2 + 0];
            qv += g_part[(kb * 64 + c) * 2 + 1];
        }
        red[grp][c]      = s;
        red[grp][64 + c] = qv;
        __syncthreads();
        if (tid < 64) {
            float sa = 0.f, sq = 0.f;
#pragma unroll
            for (int r = 0; r < 4; ++r) { sa += red[r][tid]; sq += red[r][64 + tid]; }
            const float invM = 1.0f / (float)(Bv * Nv);
            float mean = sa * invM;
            float var  = fmaf(-mean, mean, sq * invM);
            float inv  = rsqrtf(var + 1e-5f);
            float scv  = gamma[tid] * inv;
            sSB[tid]      = scv;
            sSB[64 + tid] = beta[tid] - mean * scv;
        }
        __syncthreads();
    }

#pragma unroll
    for (int it = 0; it < 16; ++it) {
        int idx = it * 256 + tid;
        int s = idx >> 6, c = idx & 63;
        tile[s][c] = fmaf(g_buf2[(bb * Nv + base + s) * 64 + c], sSB[c], sSB[64 + c]);
    }
    __syncthreads();
#pragma unroll
    for (int it = 0; it < 16; ++it) {
        int idx = it * 256 + tid;
        int c = idx >> 6, s = idx & 63;
        int off = (bb * 64 + c) * Nv + base + s;
        out[off] = x[off] + tile[s][c];
    }
}

// ---------------------------------------------------------------------------
extern "C" void kernel_launch(void* const* d_in, const int* in_sizes, int n_in,
                              void* d_out, int out_size) {
    const float* x  = (const float*)d_in[0];
    const float* w1 = (const float*)d_in[1];
    const float* g1 = (const float*)d_in[2];
    const float* b1 = (const float*)d_in[3];
    const float* w2 = (const float*)d_in[4];
    const float* g2 = (const float*)d_in[5];
    const float* b2 = (const float*)d_in[6];
    float* out = (float*)d_out;

    nchw_to_nhwc_kernel<<<288, 256>>>(x);
    conv_route_kernel<true><<<dim3(192, 8), 128>>>(w1);
    bn_stats_kernel<1><<<64, 512>>>();
    wprep_kernel<<<144, 256>>>(w2, g1, b1);
    conv_route_kernel<false><<<dim3(192, 8), 128>>>(w2);  // uses g_w2p internally
    bn_stats_kernel<2><<<64, 512>>>();
    final_kernel<<<288, 256>>>(x, g2, b2, out);
}